// round 7
// baseline (speedup 1.0000x reference)
#include <cuda_runtime.h>

#define N_STRUCT_MAX 16384

__device__ __align__(16) float g_cinv[N_STRUCT_MAX * 12];
__device__ __align__(16) float g_cvec[N_STRUCT_MAX * 32];

__device__ __forceinline__ float leaky(float x) { return fmaxf(x, 0.01f * x); }

__device__ __forceinline__ unsigned long long pack2(float lo, float hi) {
    unsigned long long r;
    asm("mov.b64 %0, {%1, %2};" : "=l"(r) : "f"(lo), "f"(hi));
    return r;
}
__device__ __forceinline__ void unpack2(unsigned long long v, float& lo, float& hi) {
    asm("mov.b64 {%0, %1}, %2;" : "=f"(lo), "=f"(hi) : "l"(v));
}
__device__ __forceinline__ unsigned long long fma2(unsigned long long a, unsigned long long b,
                                                   unsigned long long c) {
    unsigned long long d;
    asm("fma.rn.f32x2 %0, %1, %2, %3;" : "=l"(d) : "l"(a), "l"(b), "l"(c));
    return d;
}

// One warp per structure.
__global__ __launch_bounds__(256) void precompute_kernel(
    const float* __restrict__ cell,
    const float* __restrict__ w2a,
    const float* __restrict__ b2a,
    float* __restrict__ out, int S)
{
    __shared__ float sW[81 * 32];  // [t][j] = w2a[j*90+9+t]
    int tid = threadIdx.x;
    for (int i = tid; i < 81 * 32; i += blockDim.x) {
        int t = i >> 5, j = i & 31;
        sW[i] = w2a[j * 90 + 9 + t];
    }
    __syncthreads();

    int warpId = tid >> 5;
    int lane = tid & 31;
    int s = blockIdx.x * 8 + warpId;
    if (s >= S) return;

    float m[9];
#pragma unroll
    for (int i = 0; i < 9; i++) m[i] = __ldg(cell + s * 9 + i);

    float acc = b2a[lane];
#pragma unroll
    for (int p = 0; p < 9; p++) {
        float mp = m[p];
#pragma unroll
        for (int q = 0; q < 9; q++)
            acc = fmaf(sW[(p * 9 + q) * 32 + lane], mp * m[q], acc);
    }
    g_cvec[s * 32 + lane] = acc;

    if (lane < 6) out[s * 6 + lane] = 0.f;

    if (lane == 0) {
        float c00 = m[4] * m[8] - m[5] * m[7];
        float c01 = m[5] * m[6] - m[3] * m[8];
        float c02 = m[3] * m[7] - m[4] * m[6];
        float det = m[0] * c00 + m[1] * c01 + m[2] * c02;
        float id = 1.f / det;
        float4* o = (float4*)(g_cinv + s * 12);
        float4 r0, r1, r2;
        r0.x = c00 * id;
        r0.y = (m[2] * m[7] - m[1] * m[8]) * id;
        r0.z = (m[1] * m[5] - m[2] * m[4]) * id;
        r0.w = c01 * id;
        r1.x = (m[0] * m[8] - m[2] * m[6]) * id;
        r1.y = (m[2] * m[3] - m[0] * m[5]) * id;
        r1.z = c02 * id;
        r1.w = (m[1] * m[6] - m[0] * m[7]) * id;
        r2.x = (m[0] * m[4] - m[1] * m[3]) * id;
        r2.y = 0.f; r2.z = 0.f; r2.w = 0.f;
        o[0] = r0; o[1] = r1; o[2] = r2;
    }
}

// 2 atoms per thread, layer1 tiled 4x8 and fused into layer2 to minimize regs.
__global__ void __launch_bounds__(128, 6) atom_kernel(
    const float* __restrict__ atom_prop, const float* __restrict__ pos,
    const int* __restrict__ batch,
    const float* __restrict__ w0, const float* __restrict__ b0,
    const float* __restrict__ w1, const float* __restrict__ b1,
    const float* __restrict__ w1n, const float* __restrict__ b1n,
    const float* __restrict__ w2a,
    const float* __restrict__ w2b, const float* __restrict__ b2b,
    const float* __restrict__ w2c, const float* __restrict__ b2c,
    float* __restrict__ out, int n)
{
    __shared__ __align__(16) float sW1t[9 * 32];   // [k][j]
    __shared__ __align__(16) float sW2t[32 * 16];  // [k][j]
    __shared__ __align__(16) float sW3t[16 * 8];   // [k][j], j padded to 8
    __shared__ float sSmall[64];

    int tid = threadIdx.x;
    for (int i = tid; i < 288; i += blockDim.x) {
        int k = i >> 5, j = i & 31;
        sW1t[i] = w2a[j * 90 + k];
    }
    for (int i = tid; i < 512; i += blockDim.x) {
        int k = i >> 4, j = i & 15;
        sW2t[i] = w2b[j * 32 + k];
    }
    for (int i = tid; i < 128; i += blockDim.x) {
        int k = i >> 3, j = i & 7;
        sW3t[i] = (j < 6) ? w2c[j * 16 + k] : 0.f;
    }
    if (tid < 9)        sSmall[tid] = w0[tid];
    else if (tid < 18)  sSmall[tid] = w1[tid - 9];
    else if (tid < 27)  sSmall[tid] = w1n[tid - 18];
    else if (tid < 30)  sSmall[tid] = b0[tid - 27];
    else if (tid < 33)  sSmall[tid] = b1[tid - 30];
    else if (tid < 36)  sSmall[tid] = b1n[tid - 33];
    else if (tid < 52)  sSmall[tid] = b2b[tid - 36];
    else if (tid < 60)  sSmall[tid] = (tid < 58) ? b2c[tid - 52] : 0.f;
    __syncthreads();

    const float* sw0  = sSmall;
    const float* sw1  = sSmall + 9;
    const float* sw1n = sSmall + 18;
    const float* sb0  = sSmall + 27;
    const float* sb1  = sSmall + 30;
    const float* sb1n = sSmall + 33;
    const float* sb2b = sSmall + 36;
    const float* sb2c = sSmall + 52;

    int lane = tid & 31;
    int i0 = (blockIdx.x * blockDim.x + tid) * 2;
    int i1 = i0 + 1;
    bool v0 = i0 < n, v1 = i1 < n;
    int b0i, b1i;
    if (v1) {
        int2 bb = *(const int2*)(batch + i0);
        b0i = bb.x; b1i = bb.y;
    } else if (v0) {
        b0i = batch[i0]; b1i = b0i;
    } else {
        b0i = -1; b1i = -1;
    }

    float hA[6], hB[6];
#pragma unroll
    for (int k = 0; k < 6; k++) { hA[k] = 0.f; hB[k] = 0.f; }

    if (v0) {
        // ---- head ----
        const float2* pp = (const float2*)(pos + 3 * i0);
        float2 q0 = pp[0], q1 = pp[1], q2 = v1 ? pp[2] : make_float2(0.f, 0.f);
        const float2* ap = (const float2*)(atom_prop + 3 * i0);
        float2 a0 = ap[0], a1 = ap[1], a2 = v1 ? ap[2] : make_float2(0.f, 0.f);

        float pA[3] = {q0.x, q0.y, q1.x};
        float pB[3] = {q1.y, q2.x, q2.y};
        float apA[3] = {a0.x, a0.y, a1.x};
        float apB[3] = {a1.y, a2.x, a2.y};

        float xA[9], xB[9];
#pragma unroll
        for (int at = 0; at < 2; at++) {
            int bb = at ? b1i : b0i;
            const float* P = at ? pB : pA;
            const float* AP = at ? apB : apA;
            float* X = at ? xB : xA;
            const float4* civ = (const float4*)(g_cinv + bb * 12);
            float4 c0 = civ[0], c1 = civ[1], c2 = civ[2];
            float ci[9] = {c0.x, c0.y, c0.z, c0.w, c1.x, c1.y, c1.z, c1.w, c2.x};
            float th[3];
#pragma unroll
            for (int e = 0; e < 3; e++) {
                float f = fmaf(P[0], ci[e], fmaf(P[1], ci[3 + e], P[2] * ci[6 + e]));
                th[e] = f - floorf(f) - 0.5f;
            }
            X[0] = AP[0]; X[1] = AP[1]; X[2] = AP[2];
#pragma unroll
            for (int j = 0; j < 3; j++) {
                float a = leaky(fmaf(sw0[j*3], AP[0], fmaf(sw0[j*3+1], AP[1], fmaf(sw0[j*3+2], AP[2], sb0[j]))));
                float u = fmaf(sw1[j*3], th[0], fmaf(sw1[j*3+1], th[1], fmaf(sw1[j*3+2], th[2], sb1[j])));
                float v = sb1n[j] - fmaf(sw1n[j*3], th[0], fmaf(sw1n[j*3+1], th[1], sw1n[j*3+2] * th[2]));
                X[3 + j] = fmaxf(u, 0.f) * a;
                X[6 + j] = fmaxf(v, 0.f) * a;
            }
        }

        // ---- layer-2 accumulators (persistent across layer-1 tiles) ----
        unsigned long long acc2A[8], acc2B[8];
#pragma unroll
        for (int q = 0; q < 8; q++) {
            unsigned long long bb = pack2(sb2b[2*q], sb2b[2*q+1]);
            acc2A[q] = bb; acc2B[q] = bb;
        }

        // ---- layer 1 in four 8-output tiles, fused into layer 2 ----
#pragma unroll
        for (int jt = 0; jt < 4; jt++) {
            unsigned long long a1A[4], a1B[4];
            const float4* cvA = (const float4*)(g_cvec + b0i * 32) + jt * 2;
            const float4* cvB = (const float4*)(g_cvec + b1i * 32) + jt * 2;
#pragma unroll
            for (int q = 0; q < 2; q++) {
                float4 ca = cvA[q], cb = cvB[q];
                a1A[2*q]   = pack2(ca.x, ca.y);
                a1A[2*q+1] = pack2(ca.z, ca.w);
                a1B[2*q]   = pack2(cb.x, cb.y);
                a1B[2*q+1] = pack2(cb.z, cb.w);
            }
#pragma unroll
            for (int k = 0; k < 9; k++) {
                unsigned long long xa = pack2(xA[k], xA[k]);
                unsigned long long xb = pack2(xB[k], xB[k]);
                const ulonglong2* wr = (const ulonglong2*)(sW1t + k * 32 + jt * 8);
#pragma unroll
                for (int q = 0; q < 2; q++) {
                    ulonglong2 w = wr[q];
                    a1A[2*q]   = fma2(w.x, xa, a1A[2*q]);
                    a1A[2*q+1] = fma2(w.y, xa, a1A[2*q+1]);
                    a1B[2*q]   = fma2(w.x, xb, a1B[2*q]);
                    a1B[2*q+1] = fma2(w.y, xb, a1B[2*q+1]);
                }
            }
            // fuse: relu(h1 pair) -> layer 2 accumulation, a1 regs die here
#pragma unroll
            for (int p = 0; p < 4; p++) {
                float lA0, lA1, lB0, lB1;
                unpack2(a1A[p], lA0, lA1);
                unpack2(a1B[p], lB0, lB1);
                lA0 = fmaxf(lA0, 0.f); lA1 = fmaxf(lA1, 0.f);
                lB0 = fmaxf(lB0, 0.f); lB1 = fmaxf(lB1, 0.f);
                int k0 = jt * 8 + 2 * p;
#pragma unroll
                for (int r = 0; r < 2; r++) {
                    unsigned long long xa = pack2(r ? lA1 : lA0, r ? lA1 : lA0);
                    unsigned long long xb = pack2(r ? lB1 : lB0, r ? lB1 : lB0);
                    const ulonglong2* wr = (const ulonglong2*)(sW2t + (k0 + r) * 16);
#pragma unroll
                    for (int q = 0; q < 4; q++) {
                        ulonglong2 w = wr[q];
                        acc2A[2*q]   = fma2(w.x, xa, acc2A[2*q]);
                        acc2A[2*q+1] = fma2(w.y, xa, acc2A[2*q+1]);
                        acc2B[2*q]   = fma2(w.x, xb, acc2B[2*q]);
                        acc2B[2*q+1] = fma2(w.y, xb, acc2B[2*q+1]);
                    }
                }
            }
        }

        // ---- layer 3 fused from acc2 ----
        unsigned long long acc3A[4], acc3B[4];
#pragma unroll
        for (int q = 0; q < 4; q++) {
            unsigned long long bb = pack2(sb2c[2*q], sb2c[2*q+1]);
            acc3A[q] = bb; acc3B[q] = bb;
        }
#pragma unroll
        for (int p = 0; p < 8; p++) {
            float lA0, lA1, lB0, lB1;
            unpack2(acc2A[p], lA0, lA1);
            unpack2(acc2B[p], lB0, lB1);
            lA0 = leaky(lA0); lA1 = leaky(lA1);
            lB0 = leaky(lB0); lB1 = leaky(lB1);
#pragma unroll
            for (int r = 0; r < 2; r++) {
                unsigned long long xa = pack2(r ? lA1 : lA0, r ? lA1 : lA0);
                unsigned long long xb = pack2(r ? lB1 : lB0, r ? lB1 : lB0);
                const ulonglong2* wr = (const ulonglong2*)(sW3t + (2 * p + r) * 8);
#pragma unroll
                for (int q = 0; q < 2; q++) {
                    ulonglong2 w = wr[q];
                    acc3A[2*q]   = fma2(w.x, xa, acc3A[2*q]);
                    acc3A[2*q+1] = fma2(w.y, xa, acc3A[2*q+1]);
                    acc3B[2*q]   = fma2(w.x, xb, acc3B[2*q]);
                    acc3B[2*q+1] = fma2(w.y, xb, acc3B[2*q+1]);
                }
            }
        }
#pragma unroll
        for (int p = 0; p < 3; p++) {
            unpack2(acc3A[p], hA[2*p], hA[2*p+1]);
            unpack2(acc3B[p], hB[2*p], hB[2*p+1]);
        }
        if (!v1) {
#pragma unroll
            for (int k = 0; k < 6; k++) hB[k] = 0.f;
        }
    }

    // ---- segmented reduction over sorted batch (2 atoms/thread) ----
    float vscan[6];
    bool split = (b0i != b1i);
#pragma unroll
    for (int k = 0; k < 6; k++) vscan[k] = split ? hB[k] : (hA[k] + hB[k]);

    const unsigned mask = 0xffffffffu;
    unsigned mseg = __match_any_sync(mask, b1i);
    int head = __ffs(mseg) - 1;
#pragma unroll
    for (int d = 1; d < 32; d <<= 1) {
        bool take = (lane >= head + d);
#pragma unroll
        for (int k = 0; k < 6; k++) {
            float o = __shfl_up_sync(mask, vscan[k], d);
            if (take) vscan[k] += o;
        }
    }

    int bprev = __shfl_up_sync(mask, b1i, 1);
    float sprev[6];
#pragma unroll
    for (int k = 0; k < 6; k++) sprev[k] = __shfl_up_sync(mask, vscan[k], 1);
    int bnext0 = __shfl_down_sync(mask, b0i, 1);

    if (split && b0i >= 0) {
        bool carry = (lane > 0) && (bprev == b0i);
#pragma unroll
        for (int k = 0; k < 6; k++) {
            float t = hA[k] + (carry ? sprev[k] : 0.f);
            atomicAdd(&out[b0i * 6 + k], t);
        }
    }
    bool tail = (lane == 31) || (bnext0 != b1i);
    if (b1i >= 0 && tail) {
#pragma unroll
        for (int k = 0; k < 6; k++) atomicAdd(&out[b1i * 6 + k], vscan[k]);
    }
}

extern "C" void kernel_launch(void* const* d_in, const int* in_sizes, int n_in,
                              void* d_out, int out_size)
{
    const float* atom_prop = (const float*)d_in[0];
    const float* pos       = (const float*)d_in[1];
    const float* cell      = (const float*)d_in[2];
    const int*   batch     = (const int*)d_in[3];
    const float* w0  = (const float*)d_in[4];
    const float* b0  = (const float*)d_in[5];
    const float* w1  = (const float*)d_in[6];
    const float* b1  = (const float*)d_in[7];
    const float* w1n = (const float*)d_in[8];
    const float* b1n = (const float*)d_in[9];
    const float* w2a = (const float*)d_in[10];
    const float* b2a = (const float*)d_in[11];
    const float* w2b = (const float*)d_in[12];
    const float* b2b = (const float*)d_in[13];
    const float* w2c = (const float*)d_in[14];
    const float* b2c = (const float*)d_in[15];
    float* out = (float*)d_out;

    int n = in_sizes[3];        // N_ATOMS
    int S = in_sizes[2] / 9;    // N_STRUCT

    precompute_kernel<<<(S + 7) / 8, 256>>>(cell, w2a, b2a, out, S);
    atom_kernel<<<(n + 255) / 256, 128>>>(
        atom_prop, pos, batch, w0, b0, w1, b1, w1n, b1n,
        w2a, w2b, b2b, w2c, b2c, out, n);
}